// round 14
// baseline (speedup 1.0000x reference)
#include <cuda_runtime.h>
#include <cuda_bf16.h>
#include <cuda_fp16.h>
#include <cstdint>

#define TT 1024
#define EE 1024
#define HH 16
#define BB 2
#define BH (BB*HH)        // 32
#define HE (HH*EE)        // 16384
#define MROWS (BB*TT)     // 2048
#define K3Y   (3*HH*64)   // 3072 (scores triplet K, bf16)
#define NSPLIT 2
#define KSPLIT (HE/NSPLIT) // 8192

// ---------------------------------------------------------------------------
// Scratch
// ---------------------------------------------------------------------------
__device__ float          g_P   [(size_t)BH * TT * TT];   // fp32 scores
__device__ __half         g_Pp  [(size_t)BH * TT * TT];   // P single fp16
__device__ __nv_bfloat16  g_Y3a [(size_t)MROWS * K3Y];    // Y triplets A (h,l,h)
__device__ __nv_bfloat16  g_Y3b [(size_t)MROWS * K3Y];    // Y triplets B (h,h,l)
__device__ __half         g_xT  [(size_t)BB * EE * TT];   // x^T single fp16
__device__ __half         g_Wt  [(size_t)EE * HE];        // W^T single fp16
__device__ __half         g_O2h [(size_t)MROWS * HE];     // O2 single fp16
__device__ float          g_part[(size_t)NSPLIT * MROWS * EE];

// ---------------------------------------------------------------------------
// helpers
// ---------------------------------------------------------------------------
__device__ __forceinline__ unsigned short bfh(float f) {
    return __bfloat16_as_ushort(__float2bfloat16(f));
}
__device__ __forceinline__ float bff(unsigned short u) {
    return __bfloat162float(__ushort_as_bfloat16(u));
}
__device__ __forceinline__ unsigned short fph(float f) {
    return __half_as_ushort(__float2half_rn(f));
}
__device__ __forceinline__ void cp16(uint32_t dst, const void* src) {
    asm volatile("cp.async.cg.shared.global [%0], [%1], 16;" :: "r"(dst), "l"(src));
}
__device__ __forceinline__ void cpcommit() { asm volatile("cp.async.commit_group;"); }
template<int N>
__device__ __forceinline__ void cpwait() { asm volatile("cp.async.wait_group %0;" :: "n"(N)); }

__device__ __forceinline__ void ldm4(uint32_t* r, uint32_t addr) {
    asm volatile("ldmatrix.sync.aligned.m8n8.x4.shared.b16 {%0,%1,%2,%3}, [%4];"
                 : "=r"(r[0]), "=r"(r[1]), "=r"(r[2]), "=r"(r[3]) : "r"(addr));
}
template<int FT>
__device__ __forceinline__ void mma16(float* d, const uint32_t* a, const uint32_t* b) {
    if (FT == 0)
        asm volatile(
            "mma.sync.aligned.m16n8k16.row.col.f32.bf16.bf16.f32 "
            "{%0,%1,%2,%3}, {%4,%5,%6,%7}, {%8,%9}, {%0,%1,%2,%3};\n"
            : "+f"(d[0]), "+f"(d[1]), "+f"(d[2]), "+f"(d[3])
            : "r"(a[0]), "r"(a[1]), "r"(a[2]), "r"(a[3]), "r"(b[0]), "r"(b[1]));
    else
        asm volatile(
            "mma.sync.aligned.m16n8k16.row.col.f32.f16.f16.f32 "
            "{%0,%1,%2,%3}, {%4,%5,%6,%7}, {%8,%9}, {%0,%1,%2,%3};\n"
            : "+f"(d[0]), "+f"(d[1]), "+f"(d[2]), "+f"(d[3])
            : "r"(a[0]), "r"(a[1]), "r"(a[2]), "r"(a[3]), "r"(b[0]), "r"(b[1]));
}

// bf16 triplet writers (scores path)
__device__ __forceinline__ void tripA(uint32_t* o, float v0, float v1) {
    unsigned short h0 = bfh(v0), h1 = bfh(v1);
    unsigned short l0 = bfh(v0 - bff(h0)), l1 = bfh(v1 - bff(h1));
    o[0] = h0 | ((uint32_t)l0 << 16);
    o[1] = h0 | ((uint32_t)h1 << 16);
    o[2] = l1 | ((uint32_t)h1 << 16);
}
__device__ __forceinline__ void tripB(uint32_t* o, float v0, float v1) {
    unsigned short h0 = bfh(v0), h1 = bfh(v1);
    unsigned short l0 = bfh(v0 - bff(h0)), l1 = bfh(v1 - bff(h1));
    o[0] = h0 | ((uint32_t)h0 << 16);
    o[1] = l0 | ((uint32_t)h1 << 16);
    o[2] = h1 | ((uint32_t)l1 << 16);
}

// ---------------------------------------------------------------------------
// prep kernels (unchanged)
// ---------------------------------------------------------------------------
__global__ __launch_bounds__(256) void prep_y3(const float* __restrict__ x) {
    size_t i = (size_t)blockIdx.x * 256 + threadIdx.x;
    size_t row = i >> 9;
    int c = (int)(i & 511) * 2;
    float v0 = x[row * EE + c], v1 = x[row * EE + c + 1];
    tripA((uint32_t*)((char*)g_Y3a + row * (K3Y * 2) + c * 6), v0, v1);
    tripB((uint32_t*)((char*)g_Y3b + row * (K3Y * 2) + c * 6), v0, v1);
}

__global__ __launch_bounds__(256) void prep_xT(const float* __restrict__ x) {
    __shared__ float ts[64][33];
    const int b = blockIdx.z;
    const int s0 = blockIdx.x * 64;
    const int c0 = blockIdx.y * 32;
    const int tid = threadIdx.x;
    const int cl = tid & 31, rl = tid >> 5;
    #pragma unroll
    for (int r8 = 0; r8 < 8; r8++)
        ts[rl + r8 * 8][cl] =
            x[(size_t)b * (TT * EE) + (size_t)(s0 + rl + r8 * 8) * EE + c0 + cl];
    __syncthreads();
    const int crow = tid >> 3;
    const int p0 = tid & 7;
    __half* rowPtr = g_xT + ((size_t)b * EE + c0 + crow) * TT + s0;
    uint4 u;
    unsigned short* us = (unsigned short*)&u;
    #pragma unroll
    for (int e = 0; e < 8; e++) us[e] = fph(ts[p0 * 8 + e][crow]);
    *(uint4*)(rowPtr + p0 * 8) = u;
}

__global__ __launch_bounds__(256) void prep_wT(const float* __restrict__ w) {
    __shared__ float ts[64][33];
    const int k0 = blockIdx.x * 64;
    const int n0 = blockIdx.y * 32;
    const int tid = threadIdx.x;
    const int cl = tid & 31, rl = tid >> 5;
    #pragma unroll
    for (int r8 = 0; r8 < 8; r8++)
        ts[rl + r8 * 8][cl] = w[(size_t)(k0 + rl + r8 * 8) * EE + n0 + cl];
    __syncthreads();
    const int crow = tid >> 3;
    const int p0 = tid & 7;
    __half* rowPtr = g_Wt + (size_t)(n0 + crow) * HE + k0;
    uint4 u;
    unsigned short* us = (unsigned short*)&u;
    #pragma unroll
    for (int e = 0; e < 8; e++) us[e] = fph(ts[p0 * 8 + e][crow]);
    *(uint4*)(rowPtr + p0 * 8) = u;
}

// ---------------------------------------------------------------------------
// GEMM body v4: 128x64 CTA tile, BK=64, warp tile 32x32 (8 warps 4x2),
// 3-stage cp.async pipeline, 3 CTAs/SM (24 warps), SW128 swizzle.
// EPI: 0 = scores (mask + 0.25), 1 = plain fp32, 2 = single fp16 store.
// FT:  0 = bf16 mma, 1 = fp16 mma.
// ---------------------------------------------------------------------------
#define ST_A   16384                 // 128 rows x 128B
#define ST_B   8192                  // 64 rows x 128B
#define ST_SZ  (ST_A + ST_B)         // 24 KB / stage
#define GSMEM  (3 * ST_SZ + 128)     // 72 KB + align

template<int EPI, int FT>
__device__ __forceinline__ void tc_gemm(
    const uint16_t* __restrict__ A, int lda,
    const uint16_t* __restrict__ B, int ldb,
    int mBase, int nBase, int nk,
    float* __restrict__ Cf, int ldc,
    char* __restrict__ Cb, size_t cColBase, int cStrideW)
{
    extern __shared__ char smraw[];
    const uint32_t smBase =
        ((uint32_t)__cvta_generic_to_shared(smraw) + 127u) & ~127u;
    const uint32_t smEnd = smBase + 3 * ST_SZ;

    const int tid = threadIdx.x;
    const int lane = tid & 31;
    const int warp = tid >> 5;
    const int wr = warp >> 1;          // 0..3 -> m offset 32*wr
    const int wc = warp & 1;           // 0..1 -> n offset 32*wc

    const int g = lane >> 3, rl = lane & 7;
    const int baseRowA = wr * 32 + ((g & 1) << 3) + rl;
    const int cA = g >> 1;
    const int permA = baseRowA & 7;
    const int baseRowB = wc * 32 + ((g >> 1) << 3) + rl;
    const int cB = g & 1;
    const int permB = baseRowB & 7;

    // fill geometry: A 128x64 (4 cp16/thr), B 64x64 (2 cp16/thr)
    const int farow = tid >> 1;
    const int fak0  = (tid & 1) * 4;
    const int fbrow = tid >> 2;
    const int fbk0  = (tid & 3) * 2;
    uint32_t faoff[4], fboff[2];
    #pragma unroll
    for (int c = 0; c < 4; c++)
        faoff[c] = farow * 128 + (((fak0 + c) ^ (farow & 7)) << 4);
    #pragma unroll
    for (int c = 0; c < 2; c++)
        fboff[c] = fbrow * 128 + (((fbk0 + c) ^ (fbrow & 7)) << 4);
    const uint16_t* srcA = A + (size_t)(mBase + farow) * lda + fak0 * 8;
    const uint16_t* srcB = B + (size_t)(nBase + fbrow) * ldb + fbk0 * 8;

    float acc[2][4][4];
    #pragma unroll
    for (int i = 0; i < 2; i++)
        #pragma unroll
        for (int j = 0; j < 4; j++)
            #pragma unroll
            for (int k = 0; k < 4; k++) acc[i][j][k] = 0.f;

    auto fill = [&](uint32_t aB) {
        const uint32_t bB = aB + ST_A;
        #pragma unroll
        for (int c = 0; c < 4; c++) cp16(aB + faoff[c], srcA + c * 8);
        #pragma unroll
        for (int c = 0; c < 2; c++) cp16(bB + fboff[c], srcB + c * 8);
        srcA += 64;
        srcB += 64;
    };

    uint32_t fillBase = smBase;
    uint32_t compBase = smBase;
    fill(fillBase); cpcommit();
    fillBase += ST_SZ;
    if (nk > 1) { fill(fillBase); cpcommit(); fillBase += ST_SZ; }

    for (int it = 0; it < nk; it++) {
        if (it < nk - 1) cpwait<1>(); else cpwait<0>();
        __syncthreads();
        if (it + 2 < nk) {
            if (fillBase == smEnd) fillBase = smBase;
            fill(fillBase);
            cpcommit();
            fillBase += ST_SZ;
        }

        const uint32_t smA = compBase;
        const uint32_t smB = smA + ST_A;
        compBase += ST_SZ;
        if (compBase == smEnd) compBase = smBase;

        #pragma unroll
        for (int ks = 0; ks < 4; ks++) {
            uint32_t a[2][4];
            #pragma unroll
            for (int mf = 0; mf < 2; mf++)
                ldm4(a[mf], smA + (baseRowA + mf * 16) * 128
                          + (((ks * 2 + cA) ^ permA) << 4));
            uint32_t bb[2][4];
            #pragma unroll
            for (int p = 0; p < 2; p++)
                ldm4(bb[p], smB + (baseRowB + p * 16) * 128
                          + (((ks * 2 + cB) ^ permB) << 4));
            #pragma unroll
            for (int mf = 0; mf < 2; mf++)
                #pragma unroll
                for (int nf = 0; nf < 4; nf++)
                    mma16<FT>(acc[mf][nf], a[mf], &bb[nf >> 1][(nf & 1) * 2]);
        }
    }

    // epilogue
    const int lmBase = mBase + wr * 32 + (lane >> 2);
    const int lnBase = nBase + wc * 32 + (lane & 3) * 2;
    #pragma unroll
    for (int mf = 0; mf < 2; mf++) {
        #pragma unroll
        for (int nf = 0; nf < 4; nf++) {
            const int ln = lnBase + nf * 8;
            #pragma unroll
            for (int half = 0; half < 2; half++) {
                const int rGlob = lmBase + mf * 16 + half * 8;
                float v0 = acc[mf][nf][half * 2 + 0];
                float v1 = acc[mf][nf][half * 2 + 1];
                if (EPI == 0) {
                    v0 = (ln     <= rGlob) ? v0 * 0.25f : -1e30f;
                    v1 = (ln + 1 <= rGlob) ? v1 * 0.25f : -1e30f;
                    *(float2*)&Cf[(size_t)rGlob * ldc + ln] = make_float2(v0, v1);
                } else if (EPI == 1) {
                    *(float2*)&Cf[(size_t)rGlob * ldc + ln] = make_float2(v0, v1);
                } else {
                    uint32_t u = fph(v0) | ((uint32_t)fph(v1) << 16);
                    *(uint32_t*)(Cb + (size_t)rGlob * cStrideW
                                 + cColBase + 2 * (size_t)(ln - nBase)) = u;
                }
            }
        }
    }
}

// ---------------------------------------------------------------------------
// scores for one head group: grid (16, 8, 16), 64-col tiles.
// keep iff tile intersects lower triangle: bx*64 <= by*128+127.
// ---------------------------------------------------------------------------
__global__ __launch_bounds__(256, 3) void scores_bf16(int hg) {
    if ((int)blockIdx.x > 2 * (int)blockIdx.y + 1) return;
    const int b = blockIdx.z >> 3;
    const int h = hg * 8 + (blockIdx.z & 7);
    const int bh = b * 16 + h;
    tc_gemm<0, 0>((const uint16_t*)(g_Y3a + (size_t)b * TT * K3Y + h * 192), K3Y,
                  (const uint16_t*)(g_Y3b + (size_t)b * TT * K3Y + h * 192), K3Y,
                  blockIdx.y * 128, blockIdx.x * 64, 3,
                  g_P + (size_t)bh * TT * TT, TT, nullptr, 0, 0);
}

// ---------------------------------------------------------------------------
// softmax for one head group (unchanged).
// ---------------------------------------------------------------------------
__global__ __launch_bounds__(256) void softmax_kernel(int hg) {
    const int r = blockIdx.x * 8 + (threadIdx.x >> 5);
    const int lane = threadIdx.x & 31;
    const int bhIdx = r >> 10;
    const int t = r & (TT - 1);
    const int bh = (bhIdx >> 3) * 16 + hg * 8 + (bhIdx & 7);
    const int row = bh * TT + t;
    const int nch = (t >> 7) + 1;
    const float* __restrict__ p = g_P + (size_t)row * TT;

    float v[32];
    float m = -1e30f;
    #pragma unroll
    for (int c = 0; c < 8; c++) {
        if (c < nch) {
            float4 f = *(const float4*)(p + c * 128 + lane * 4);
            v[4*c] = f.x; v[4*c+1] = f.y; v[4*c+2] = f.z; v[4*c+3] = f.w;
            m = fmaxf(m, fmaxf(fmaxf(f.x, f.y), fmaxf(f.z, f.w)));
        }
    }
    #pragma unroll
    for (int o = 16; o > 0; o >>= 1) m = fmaxf(m, __shfl_xor_sync(~0u, m, o));

    float sum = 0.f;
    #pragma unroll
    for (int c = 0; c < 8; c++) {
        if (c < nch) {
            #pragma unroll
            for (int i = 0; i < 4; i++) {
                v[4*c+i] = __expf(v[4*c+i] - m);
                sum += v[4*c+i];
            }
        }
    }
    #pragma unroll
    for (int o = 16; o > 0; o >>= 1) sum += __shfl_xor_sync(~0u, sum, o);
    const float inv = 1.0f / sum;

    __half* ob = g_Pp + (size_t)row * TT;
    #pragma unroll
    for (int c = 0; c < 8; c++) {
        if (c < nch) {
            uint2 u;
            u.x = fph(v[4*c]   * inv) | ((uint32_t)fph(v[4*c+1] * inv) << 16);
            u.y = fph(v[4*c+2] * inv) | ((uint32_t)fph(v[4*c+3] * inv) << 16);
            *(uint2*)(ob + c * 128 + lane * 4) = u;
        }
    }
}

// ---------------------------------------------------------------------------
// pv for one head group: 1-D LPT grid, 2048 CTAs (64-col tiles), heavy first.
// ---------------------------------------------------------------------------
__global__ __launch_bounds__(256, 3) void pv_f16(int hg) {
    const int gid = blockIdx.x;
    const int ty = 7 - (gid >> 8);
    const int sub = gid & 255;
    const int bx = sub & 15;
    const int z = sub >> 4;
    const int b = z >> 3;
    const int h = hg * 8 + (z & 7);
    const int bh = b * 16 + h;
    const int mBase = ty * 128;
    tc_gemm<2, 1>((const uint16_t*)(g_Pp + (size_t)bh * TT * TT), TT,
                  (const uint16_t*)(g_xT + (size_t)b * EE * TT), TT,
                  mBase, bx * 64, 2 * (ty + 1),
                  nullptr, 0,
                  (char*)g_O2h + (size_t)b * TT * (HE * 2),
                  2 * ((size_t)h * EE + bx * 64), HE * 2);
}

// ---------------------------------------------------------------------------
// out for one split: grid (16, 16), 64-col tiles, nk = 128.
// ---------------------------------------------------------------------------
__global__ __launch_bounds__(256, 3) void out_f16(int sp) {
    tc_gemm<1, 1>((const uint16_t*)(g_O2h + (size_t)sp * KSPLIT), HE,
                  (const uint16_t*)(g_Wt + (size_t)sp * KSPLIT), HE,
                  blockIdx.y * 128, blockIdx.x * 64, KSPLIT / 64,
                  g_part + (size_t)sp * MROWS * EE, EE, nullptr, 0, 0);
}

// ---------------------------------------------------------------------------
__global__ __launch_bounds__(256) void reduce_out(float* __restrict__ out) {
    const size_t i = ((size_t)blockIdx.x * 256 + threadIdx.x) * 2;
    const float4* p = (const float4*)g_part;
    #pragma unroll
    for (int k = 0; k < 2; k++) {
        float4 a = p[i + k];
        float4 b = p[(size_t)(MROWS * EE / 4) + i + k];
        ((float4*)out)[i + k] =
            make_float4(a.x + b.x, a.y + b.y, a.z + b.z, a.w + b.w);
    }
}

// ---------------------------------------------------------------------------
extern "C" void kernel_launch(void* const* d_in, const int* in_sizes, int n_in,
                              void* d_out, int out_size) {
    const float* x = (const float*)d_in[0];
    // d_in[1] = mask : static causal triu(k=1), encoded analytically.
    const float* w = (const float*)d_in[2];
    float* out = (float*)d_out;

    static cudaStream_t s1 = nullptr, s2 = nullptr, s3 = nullptr;
    static cudaEvent_t e0, eXT, eWT, eY, eG1;
    if (!s1) {
        cudaStreamCreateWithFlags(&s1, cudaStreamNonBlocking);
        cudaStreamCreateWithFlags(&s2, cudaStreamNonBlocking);
        cudaStreamCreateWithFlags(&s3, cudaStreamNonBlocking);
        cudaEventCreateWithFlags(&e0,  cudaEventDisableTiming);
        cudaEventCreateWithFlags(&eXT, cudaEventDisableTiming);
        cudaEventCreateWithFlags(&eWT, cudaEventDisableTiming);
        cudaEventCreateWithFlags(&eY,  cudaEventDisableTiming);
        cudaEventCreateWithFlags(&eG1, cudaEventDisableTiming);
        cudaFuncSetAttribute(scores_bf16, cudaFuncAttributeMaxDynamicSharedMemorySize, GSMEM);
        cudaFuncSetAttribute(pv_f16,      cudaFuncAttributeMaxDynamicSharedMemorySize, GSMEM);
        cudaFuncSetAttribute(out_f16,     cudaFuncAttributeMaxDynamicSharedMemorySize, GSMEM);
    }

    // critical path first: y3 gates both chains
    prep_y3<<<(MROWS * EE / 2) / 256, 256>>>(x);
    cudaEventRecord(eY, 0);

    // fork side preps behind y3 (they overlap scores)
    cudaEventRecord(e0, 0);
    cudaStreamWaitEvent(s1, e0, 0);
    cudaStreamWaitEvent(s2, e0, 0);
    prep_xT<<<dim3(16, 32, 2), 256, 0, s1>>>(x);
    cudaEventRecord(eXT, s1);
    prep_wT<<<dim3(256, 32), 256, 0, s2>>>(w);
    cudaEventRecord(eWT, s2);

    // group-1 chain on s3
    cudaStreamWaitEvent(s3, eY, 0);
    scores_bf16<<<dim3(16, 8, 16), 256, GSMEM, s3>>>(1);
    softmax_kernel<<<2048, 256, 0, s3>>>(1);
    cudaStreamWaitEvent(s3, eXT, 0);
    pv_f16<<<2048, 256, GSMEM, s3>>>(1);
    cudaStreamWaitEvent(s3, eWT, 0);
    out_f16<<<dim3(16, 16), 256, GSMEM, s3>>>(1);
    cudaEventRecord(eG1, s3);

    // group-0 chain on main
    scores_bf16<<<dim3(16, 8, 16), 256, GSMEM>>>(0);
    softmax_kernel<<<2048, 256>>>(0);
    cudaStreamWaitEvent(0, eXT, 0);
    pv_f16<<<2048, 256, GSMEM>>>(0);
    cudaStreamWaitEvent(0, eWT, 0);
    out_f16<<<dim3(16, 16), 256, GSMEM>>>(0);

    // join and reduce
    cudaStreamWaitEvent(0, eG1, 0);
    reduce_out<<<(MROWS * EE / 8) / 256, 256>>>(out);
}

// round 15
// speedup vs baseline: 1.0822x; 1.0822x over previous
#include <cuda_runtime.h>
#include <cuda_bf16.h>
#include <cuda_fp16.h>
#include <cstdint>

#define TT 1024
#define EE 1024
#define HH 16
#define BB 2
#define BH (BB*HH)        // 32
#define HE (HH*EE)        // 16384
#define MROWS (BB*TT)     // 2048
#define K3Y   (3*HH*64)   // 3072 (scores triplet K, bf16)
#define NSPLIT 2
#define KSPLIT (HE/NSPLIT) // 8192

// ---------------------------------------------------------------------------
// Scratch
// ---------------------------------------------------------------------------
__device__ float          g_P   [(size_t)BH * TT * TT];   // fp32 scores
__device__ __half         g_Pp  [(size_t)BH * TT * TT];   // P single fp16
__device__ __nv_bfloat16  g_Y3a [(size_t)MROWS * K3Y];    // Y triplets A (h,l,h)
__device__ __nv_bfloat16  g_Y3b [(size_t)MROWS * K3Y];    // Y triplets B (h,h,l)
__device__ __half         g_xT  [(size_t)BB * EE * TT];   // x^T single fp16
__device__ __half         g_Wt  [(size_t)EE * HE];        // W^T single fp16
__device__ __half         g_O2h [(size_t)MROWS * HE];     // O2 single fp16

// ---------------------------------------------------------------------------
// helpers
// ---------------------------------------------------------------------------
__device__ __forceinline__ unsigned short bfh(float f) {
    return __bfloat16_as_ushort(__float2bfloat16(f));
}
__device__ __forceinline__ float bff(unsigned short u) {
    return __bfloat162float(__ushort_as_bfloat16(u));
}
__device__ __forceinline__ unsigned short fph(float f) {
    return __half_as_ushort(__float2half_rn(f));
}
__device__ __forceinline__ void cp16(uint32_t dst, const void* src) {
    asm volatile("cp.async.cg.shared.global [%0], [%1], 16;" :: "r"(dst), "l"(src));
}
__device__ __forceinline__ void cpcommit() { asm volatile("cp.async.commit_group;"); }
template<int N>
__device__ __forceinline__ void cpwait() { asm volatile("cp.async.wait_group %0;" :: "n"(N)); }

__device__ __forceinline__ void ldm4(uint32_t* r, uint32_t addr) {
    asm volatile("ldmatrix.sync.aligned.m8n8.x4.shared.b16 {%0,%1,%2,%3}, [%4];"
                 : "=r"(r[0]), "=r"(r[1]), "=r"(r[2]), "=r"(r[3]) : "r"(addr));
}
template<int FT>
__device__ __forceinline__ void mma16(float* d, const uint32_t* a, const uint32_t* b) {
    if (FT == 0)
        asm volatile(
            "mma.sync.aligned.m16n8k16.row.col.f32.bf16.bf16.f32 "
            "{%0,%1,%2,%3}, {%4,%5,%6,%7}, {%8,%9}, {%0,%1,%2,%3};\n"
            : "+f"(d[0]), "+f"(d[1]), "+f"(d[2]), "+f"(d[3])
            : "r"(a[0]), "r"(a[1]), "r"(a[2]), "r"(a[3]), "r"(b[0]), "r"(b[1]));
    else
        asm volatile(
            "mma.sync.aligned.m16n8k16.row.col.f32.f16.f16.f32 "
            "{%0,%1,%2,%3}, {%4,%5,%6,%7}, {%8,%9}, {%0,%1,%2,%3};\n"
            : "+f"(d[0]), "+f"(d[1]), "+f"(d[2]), "+f"(d[3])
            : "r"(a[0]), "r"(a[1]), "r"(a[2]), "r"(a[3]), "r"(b[0]), "r"(b[1]));
}

// bf16 triplet writers (scores path)
__device__ __forceinline__ void tripA(uint32_t* o, float v0, float v1) {
    unsigned short h0 = bfh(v0), h1 = bfh(v1);
    unsigned short l0 = bfh(v0 - bff(h0)), l1 = bfh(v1 - bff(h1));
    o[0] = h0 | ((uint32_t)l0 << 16);
    o[1] = h0 | ((uint32_t)h1 << 16);
    o[2] = l1 | ((uint32_t)h1 << 16);
}
__device__ __forceinline__ void tripB(uint32_t* o, float v0, float v1) {
    unsigned short h0 = bfh(v0), h1 = bfh(v1);
    unsigned short l0 = bfh(v0 - bff(h0)), l1 = bfh(v1 - bff(h1));
    o[0] = h0 | ((uint32_t)h0 << 16);
    o[1] = l0 | ((uint32_t)h1 << 16);
    o[2] = h1 | ((uint32_t)l1 << 16);
}

// ---------------------------------------------------------------------------
// prep kernels
// ---------------------------------------------------------------------------
__global__ __launch_bounds__(256) void prep_y3(const float* __restrict__ x) {
    size_t i = (size_t)blockIdx.x * 256 + threadIdx.x;
    size_t row = i >> 9;
    int c = (int)(i & 511) * 2;
    float v0 = x[row * EE + c], v1 = x[row * EE + c + 1];
    tripA((uint32_t*)((char*)g_Y3a + row * (K3Y * 2) + c * 6), v0, v1);
    tripB((uint32_t*)((char*)g_Y3b + row * (K3Y * 2) + c * 6), v0, v1);
}

__global__ __launch_bounds__(256) void prep_xT(const float* __restrict__ x) {
    __shared__ float ts[64][33];
    const int b = blockIdx.z;
    const int s0 = blockIdx.x * 64;
    const int c0 = blockIdx.y * 32;
    const int tid = threadIdx.x;
    const int cl = tid & 31, rl = tid >> 5;
    #pragma unroll
    for (int r8 = 0; r8 < 8; r8++)
        ts[rl + r8 * 8][cl] =
            x[(size_t)b * (TT * EE) + (size_t)(s0 + rl + r8 * 8) * EE + c0 + cl];
    __syncthreads();
    const int crow = tid >> 3;
    const int p0 = tid & 7;
    __half* rowPtr = g_xT + ((size_t)b * EE + c0 + crow) * TT + s0;
    uint4 u;
    unsigned short* us = (unsigned short*)&u;
    #pragma unroll
    for (int e = 0; e < 8; e++) us[e] = fph(ts[p0 * 8 + e][crow]);
    *(uint4*)(rowPtr + p0 * 8) = u;
}

__global__ __launch_bounds__(256) void prep_wT(const float* __restrict__ w) {
    __shared__ float ts[64][33];
    const int k0 = blockIdx.x * 64;
    const int n0 = blockIdx.y * 32;
    const int tid = threadIdx.x;
    const int cl = tid & 31, rl = tid >> 5;
    #pragma unroll
    for (int r8 = 0; r8 < 8; r8++)
        ts[rl + r8 * 8][cl] = w[(size_t)(k0 + rl + r8 * 8) * EE + n0 + cl];
    __syncthreads();
    const int crow = tid >> 3;
    const int p0 = tid & 7;
    __half* rowPtr = g_Wt + (size_t)(n0 + crow) * HE + k0;
    uint4 u;
    unsigned short* us = (unsigned short*)&u;
    #pragma unroll
    for (int e = 0; e < 8; e++) us[e] = fph(ts[p0 * 8 + e][crow]);
    *(uint4*)(rowPtr + p0 * 8) = u;
}

// zero d_out (poisoned by harness); gates the out kernels only.
__global__ __launch_bounds__(256) void zero_out(float* __restrict__ out) {
    const size_t i = (size_t)blockIdx.x * 256 + threadIdx.x;
    ((float4*)out)[i] = make_float4(0.f, 0.f, 0.f, 0.f);
}

// ---------------------------------------------------------------------------
// GEMM body (round-13 engine): 128x128 CTA tile, BK=64, warp tile 64x32
// (8 warps 2x4), 3-stage cp.async pipeline, rotating stage pointers.
// EPI: 0 = scores (mask + 0.25), 2 = single fp16 store, 3 = atomicAdd fp32.
// FT:  0 = bf16 mma, 1 = fp16 mma.
// ---------------------------------------------------------------------------
#define ST_A   16384
#define ST_B   16384
#define ST_SZ  (ST_A + ST_B)
#define GSMEM  (3 * ST_SZ + 128)

template<int EPI, int FT>
__device__ __forceinline__ void tc_gemm(
    const uint16_t* __restrict__ A, int lda,
    const uint16_t* __restrict__ B, int ldb,
    int mBase, int nBase, int nk,
    float* __restrict__ Cf, int ldc,
    char* __restrict__ Cb, size_t cColBase, int cStrideW)
{
    extern __shared__ char smraw[];
    const uint32_t smBase =
        ((uint32_t)__cvta_generic_to_shared(smraw) + 127u) & ~127u;
    const uint32_t smEnd = smBase + 3 * ST_SZ;

    const int tid = threadIdx.x;
    const int lane = tid & 31;
    const int warp = tid >> 5;
    const int wr = warp >> 2;
    const int wc = warp & 3;

    const int g = lane >> 3, rl = lane & 7;
    const int baseRowA = wr * 64 + ((g & 1) << 3) + rl;
    const int cA = g >> 1;
    const int permA = baseRowA & 7;
    const int baseRowB = wc * 32 + ((g >> 1) << 3) + rl;
    const int cB = g & 1;
    const int permB = baseRowB & 7;

    const int frow = tid >> 1;
    const int fk0  = (tid & 1) * 4;
    uint32_t foff[4];
    #pragma unroll
    for (int c = 0; c < 4; c++)
        foff[c] = frow * 128 + (((fk0 + c) ^ (frow & 7)) << 4);
    const uint16_t* srcA = A + (size_t)(mBase + frow) * lda + fk0 * 8;
    const uint16_t* srcB = B + (size_t)(nBase + frow) * ldb + fk0 * 8;

    float acc[4][4][4];
    #pragma unroll
    for (int i = 0; i < 4; i++)
        #pragma unroll
        for (int j = 0; j < 4; j++)
            #pragma unroll
            for (int k = 0; k < 4; k++) acc[i][j][k] = 0.f;

    auto fill = [&](uint32_t aB) {
        const uint32_t bB = aB + ST_A;
        #pragma unroll
        for (int c = 0; c < 4; c++) {
            cp16(aB + foff[c], srcA + c * 8);
            cp16(bB + foff[c], srcB + c * 8);
        }
        srcA += 64;
        srcB += 64;
    };

    uint32_t fillBase = smBase;
    uint32_t compBase = smBase;
    fill(fillBase); cpcommit();
    fillBase += ST_SZ;
    if (nk > 1) { fill(fillBase); cpcommit(); fillBase += ST_SZ; }

    for (int it = 0; it < nk; it++) {
        if (it < nk - 1) cpwait<1>(); else cpwait<0>();
        __syncthreads();
        if (it + 2 < nk) {
            if (fillBase == smEnd) fillBase = smBase;
            fill(fillBase);
            cpcommit();
            fillBase += ST_SZ;
        }

        const uint32_t smA = compBase;
        const uint32_t smB = smA + ST_A;
        compBase += ST_SZ;
        if (compBase == smEnd) compBase = smBase;

        #pragma unroll
        for (int ks = 0; ks < 4; ks++) {
            uint32_t a[4][4];
            #pragma unroll
            for (int mf = 0; mf < 4; mf++)
                ldm4(a[mf], smA + (baseRowA + mf * 16) * 128
                          + (((ks * 2 + cA) ^ permA) << 4));
            uint32_t bb[2][4];
            #pragma unroll
            for (int p = 0; p < 2; p++)
                ldm4(bb[p], smB + (baseRowB + p * 16) * 128
                          + (((ks * 2 + cB) ^ permB) << 4));
            #pragma unroll
            for (int mf = 0; mf < 4; mf++)
                #pragma unroll
                for (int nf = 0; nf < 4; nf++)
                    mma16<FT>(acc[mf][nf], a[mf], &bb[nf >> 1][(nf & 1) * 2]);
        }
    }

    // epilogue
    const int lmBase = mBase + wr * 64 + (lane >> 2);
    const int lnBase = nBase + wc * 32 + (lane & 3) * 2;
    #pragma unroll
    for (int mf = 0; mf < 4; mf++) {
        #pragma unroll
        for (int nf = 0; nf < 4; nf++) {
            const int ln = lnBase + nf * 8;
            #pragma unroll
            for (int half = 0; half < 2; half++) {
                const int rGlob = lmBase + mf * 16 + half * 8;
                float v0 = acc[mf][nf][half * 2 + 0];
                float v1 = acc[mf][nf][half * 2 + 1];
                if (EPI == 0) {
                    v0 = (ln     <= rGlob) ? v0 * 0.25f : -1e30f;
                    v1 = (ln + 1 <= rGlob) ? v1 * 0.25f : -1e30f;
                    *(float2*)&Cf[(size_t)rGlob * ldc + ln] = make_float2(v0, v1);
                } else if (EPI == 3) {
                    float* dst = &Cf[(size_t)rGlob * ldc + ln];
                    atomicAdd(dst,     v0);
                    atomicAdd(dst + 1, v1);
                } else {
                    uint32_t u = fph(v0) | ((uint32_t)fph(v1) << 16);
                    *(uint32_t*)(Cb + (size_t)rGlob * cStrideW
                                 + cColBase + 2 * (size_t)(ln - nBase)) = u;
                }
            }
        }
    }
}

// ---------------------------------------------------------------------------
// scores for one head group: grid (8, 8, 16).
// ---------------------------------------------------------------------------
__global__ __launch_bounds__(256, 2) void scores_bf16(int hg) {
    if (blockIdx.x > blockIdx.y) return;
    const int b = blockIdx.z >> 3;
    const int h = hg * 8 + (blockIdx.z & 7);
    const int bh = b * 16 + h;
    tc_gemm<0, 0>((const uint16_t*)(g_Y3a + (size_t)b * TT * K3Y + h * 192), K3Y,
                  (const uint16_t*)(g_Y3b + (size_t)b * TT * K3Y + h * 192), K3Y,
                  blockIdx.y * 128, blockIdx.x * 128, 3,
                  g_P + (size_t)bh * TT * TT, TT, nullptr, 0, 0);
}

// ---------------------------------------------------------------------------
// softmax for one head group: 2048 blocks x 256 (8 warp-rows per block).
// ---------------------------------------------------------------------------
__global__ __launch_bounds__(256) void softmax_kernel(int hg) {
    const int r = blockIdx.x * 8 + (threadIdx.x >> 5);
    const int lane = threadIdx.x & 31;
    const int bhIdx = r >> 10;
    const int t = r & (TT - 1);
    const int bh = (bhIdx >> 3) * 16 + hg * 8 + (bhIdx & 7);
    const int row = bh * TT + t;
    const int nch = (t >> 7) + 1;
    const float* __restrict__ p = g_P + (size_t)row * TT;

    float v[32];
    float m = -1e30f;
    #pragma unroll
    for (int c = 0; c < 8; c++) {
        if (c < nch) {
            float4 f = *(const float4*)(p + c * 128 + lane * 4);
            v[4*c] = f.x; v[4*c+1] = f.y; v[4*c+2] = f.z; v[4*c+3] = f.w;
            m = fmaxf(m, fmaxf(fmaxf(f.x, f.y), fmaxf(f.z, f.w)));
        }
    }
    #pragma unroll
    for (int o = 16; o > 0; o >>= 1) m = fmaxf(m, __shfl_xor_sync(~0u, m, o));

    float sum = 0.f;
    #pragma unroll
    for (int c = 0; c < 8; c++) {
        if (c < nch) {
            #pragma unroll
            for (int i = 0; i < 4; i++) {
                v[4*c+i] = __expf(v[4*c+i] - m);
                sum += v[4*c+i];
            }
        }
    }
    #pragma unroll
    for (int o = 16; o > 0; o >>= 1) sum += __shfl_xor_sync(~0u, sum, o);
    const float inv = 1.0f / sum;

    __half* ob = g_Pp + (size_t)row * TT;
    #pragma unroll
    for (int c = 0; c < 8; c++) {
        if (c < nch) {
            uint2 u;
            u.x = fph(v[4*c]   * inv) | ((uint32_t)fph(v[4*c+1] * inv) << 16);
            u.y = fph(v[4*c+2] * inv) | ((uint32_t)fph(v[4*c+3] * inv) << 16);
            *(uint2*)(ob + c * 128 + lane * 4) = u;
        }
    }
}

// ---------------------------------------------------------------------------
// pv for one head group: 1-D LPT grid, 1024 CTAs, heaviest first.
// ---------------------------------------------------------------------------
__global__ __launch_bounds__(256, 2) void pv_f16(int hg) {
    const int gid = blockIdx.x;
    const int ty = 7 - (gid >> 7);
    const int sub = gid & 127;
    const int bx = sub & 7;
    const int z = sub >> 3;
    const int b = z >> 3;
    const int h = hg * 8 + (z & 7);
    const int bh = b * 16 + h;
    const int mBase = ty * 128;
    tc_gemm<2, 1>((const uint16_t*)(g_Pp + (size_t)bh * TT * TT), TT,
                  (const uint16_t*)(g_xT + (size_t)b * EE * TT), TT,
                  mBase, bx * 128, 2 * (ty + 1),
                  nullptr, 0,
                  (char*)g_O2h + (size_t)b * TT * (HE * 2),
                  2 * ((size_t)h * EE + bx * 128), HE * 2);
}

// ---------------------------------------------------------------------------
// out for one split (== head group): grid (8, 16), nk = 128.
// Epilogue atomic-adds partials directly into d_out (zeroed beforehand).
// ---------------------------------------------------------------------------
__global__ __launch_bounds__(256, 2) void out_f16(int sp, float* __restrict__ out) {
    tc_gemm<3, 1>((const uint16_t*)(g_O2h + (size_t)sp * KSPLIT), HE,
                  (const uint16_t*)(g_Wt + (size_t)sp * KSPLIT), HE,
                  blockIdx.y * 128, blockIdx.x * 64 + (sp ? 8192 : 0) * 0, 0, // placeholder avoided below
                  nullptr, 0, nullptr, 0, 0);
}

// NOTE: out_f16 replaced by out_f16b below (kept signature simple).
__global__ __launch_bounds__(256, 2) void out_f16b(int sp, float* __restrict__ out) {
    tc_gemm<3, 1>((const uint16_t*)(g_O2h + (size_t)sp * KSPLIT), HE,
                  (const uint16_t*)(g_Wt + (size_t)sp * KSPLIT), HE,
                  blockIdx.y * 128, blockIdx.x * 128, KSPLIT / 64,
                  out, EE, nullptr, 0, 0);
}

// ---------------------------------------------------------------------------
extern "C" void kernel_launch(void* const* d_in, const int* in_sizes, int n_in,
                              void* d_out, int out_size) {
    const float* x = (const float*)d_in[0];
    // d_in[1] = mask : static causal triu(k=1), encoded analytically.
    const float* w = (const float*)d_in[2];
    float* out = (float*)d_out;

    static cudaStream_t s1 = nullptr, s2 = nullptr, s3 = nullptr;
    static cudaEvent_t e0, eXT, eWT, eY, eG1;
    if (!s1) {
        cudaStreamCreateWithFlags(&s1, cudaStreamNonBlocking);
        cudaStreamCreateWithFlags(&s2, cudaStreamNonBlocking);
        cudaStreamCreateWithFlags(&s3, cudaStreamNonBlocking);
        cudaEventCreateWithFlags(&e0,  cudaEventDisableTiming);
        cudaEventCreateWithFlags(&eXT, cudaEventDisableTiming);
        cudaEventCreateWithFlags(&eWT, cudaEventDisableTiming);
        cudaEventCreateWithFlags(&eY,  cudaEventDisableTiming);
        cudaEventCreateWithFlags(&eG1, cudaEventDisableTiming);
        cudaFuncSetAttribute(scores_bf16, cudaFuncAttributeMaxDynamicSharedMemorySize, GSMEM);
        cudaFuncSetAttribute(pv_f16,      cudaFuncAttributeMaxDynamicSharedMemorySize, GSMEM);
        cudaFuncSetAttribute(out_f16b,    cudaFuncAttributeMaxDynamicSharedMemorySize, GSMEM);
    }

    // critical path first: y3 gates both chains
    prep_y3<<<(MROWS * EE / 2) / 256, 256>>>(x);
    cudaEventRecord(eY, 0);

    // fork side preps behind y3 (they overlap scores)
    cudaEventRecord(e0, 0);
    cudaStreamWaitEvent(s1, e0, 0);
    cudaStreamWaitEvent(s2, e0, 0);
    prep_xT<<<dim3(16, 32, 2), 256, 0, s1>>>(x);
    cudaEventRecord(eXT, s1);
    zero_out<<<(MROWS * EE / 4) / 256, 256, 0, s2>>>(out);
    prep_wT<<<dim3(256, 32), 256, 0, s2>>>(w);
    cudaEventRecord(eWT, s2);   // covers zero_out + prep_wT

    // group-1 chain on s3
    cudaStreamWaitEvent(s3, eY, 0);
    scores_bf16<<<dim3(8, 8, 16), 256, GSMEM, s3>>>(1);
    softmax_kernel<<<2048, 256, 0, s3>>>(1);
    cudaStreamWaitEvent(s3, eXT, 0);
    pv_f16<<<1024, 256, GSMEM, s3>>>(1);
    cudaStreamWaitEvent(s3, eWT, 0);
    out_f16b<<<dim3(8, 16), 256, GSMEM, s3>>>(1, out);
    cudaEventRecord(eG1, s3);

    // group-0 chain on main
    scores_bf16<<<dim3(8, 8, 16), 256, GSMEM>>>(0);
    softmax_kernel<<<2048, 256>>>(0);
    cudaStreamWaitEvent(0, eXT, 0);
    pv_f16<<<1024, 256, GSMEM>>>(0);
    cudaStreamWaitEvent(0, eWT, 0);
    out_f16b<<<dim3(8, 16), 256, GSMEM>>>(0, out);

    // join group-1 into the main stream so the graph's leaf covers all work
    cudaStreamWaitEvent(0, eG1, 0);
}